// round 15
// baseline (speedup 1.0000x reference)
#include <cuda_runtime.h>
#include <cuda_fp16.h>
#include <math.h>

#define NMAX 100000
#define EMAX 3200000
#define F_IN 512
#define HID 16
#define NLAB 64

// ---------------- device scratch (no allocations allowed) ----------------
// ONLY referenced inside device code (GB300 ATS silently accepts host-shadow
// addresses — never pass these as kernel args).
// Zero-at-launch invariants: g_deg_*, g_lb zero at launch start (self-clean);
// c_scan reset by k_fused1 each launch (kernel-boundary ordered).
__device__ float g_norm_src[NMAX];
__device__ float g_norm_dst[NMAX];
__device__ int   g_deg_out[NMAX];
__device__ int   g_deg_in[NMAX];
__device__ int   g_row_start[NMAX];
__device__ unsigned long long g_lb[512];   // scan lookback: (flag<<32)|value
__device__ int   g_csr[EMAX];              // BYTE offsets (src*32)
__device__ int   g_dslot[EMAX];            // (dst<<13) | slot
__device__ uint2 g_hpreh[NMAX * 4];        // (X@W1)[*ns after scan] fp16 rows
__device__ uint2 g_hmidh[NMAX * 4];        // relu(...)*ns fp16 rows
__device__ int   c_scan;                   // scan-role completion counter

// ---------------- helpers ----------------
__device__ __forceinline__ unsigned long long pack2(float v) {
    unsigned long long r;
    asm("mov.b64 %0, {%1, %1};" : "=l"(r) : "f"(v));
    return r;
}
__device__ __forceinline__ void fma2(unsigned long long& acc,
                                     unsigned long long a,
                                     unsigned long long b) {
    asm("fma.rn.f32x2 %0, %1, %2, %0;" : "+l"(acc) : "l"(a), "l"(b));
}
__device__ __forceinline__ float2 unpack2(unsigned long long v) {
    float2 r;
    asm("mov.b64 {%0, %1}, %2;" : "=f"(r.x), "=f"(r.y) : "l"(v));
    return r;
}
__device__ __forceinline__ unsigned long long packf2(float a, float b) {
    unsigned long long r;
    asm("mov.b64 %0, {%1, %2};" : "=l"(r) : "f"(a), "f"(b));
    return r;
}
__device__ __forceinline__ unsigned h2u(__half2 h) { return *(unsigned*)&h; }
__device__ __forceinline__ __half2 u2h(unsigned u) { return *(__half2*)&u; }
__device__ __forceinline__ uint2 pack_half4(float a, float b, float c, float d) {
    uint2 r;
    r.x = h2u(__floats2half2_rn(a, b));
    r.y = h2u(__floats2half2_rn(c, d));
    return r;
}

// Per-block edge-dtype probe (32 entries). Order: i64 -> i32 -> f32 -> f64.
__device__ __forceinline__ int probe_fmt(const void* __restrict__ src,
                                         int ecount, int n, int* shflags) {
    int tid = threadIdx.x;
    if (tid < 4) shflags[tid] = 1;
    __syncthreads();
    int nprobe = ecount < 32 ? ecount : 32;
    if (tid < nprobe) {
        long long v64 = ((const long long*)src)[tid];
        if (v64 < 0 || v64 >= (long long)n) atomicAnd(&shflags[0], 0);
        int v32 = ((const int*)src)[tid];
        if (v32 < 0 || v32 >= n) atomicAnd(&shflags[1], 0);
        float f = ((const float*)src)[tid];
        if (!(f >= 0.f && f < (float)n && f == floorf(f))) atomicAnd(&shflags[2], 0);
        double d = ((const double*)src)[tid];
        if (!(d >= 0.0 && d < (double)n && d == floor(d))) atomicAnd(&shflags[3], 0);
    }
    __syncthreads();
    return shflags[0] ? 0 : (shflags[1] ? 1 : (shflags[2] ? 2 : 3));
}

__device__ __forceinline__ int load_idx(const void* __restrict__ p, int fmt,
                                        int e, int n) {
    int v;
    if (fmt == 0)      v = (int)__ldcs((const long long*)p + e);
    else if (fmt == 1) v = __ldcs((const int*)p + e);
    else if (fmt == 2) v = (int)__ldcs((const float*)p + e);
    else               v = (int)__ldcs((const double*)p + e);
    return v < 0 ? 0 : (v >= n ? n - 1 : v);
}

// ---------------- fused 1: gemm1 (blocks first) || conv+degree ----------------

// GEMM1: 2 rows/thread, packed f32x2 FMA, writes fp16 UNSCALED rows.
__device__ __forceinline__ void gemm1_part(const float* __restrict__ X,
                                           const float* __restrict__ W1,
                                           float* __restrict__ sW1,
                                           int gblk, int n) {
    int tid = threadIdx.x;  // 256
    #pragma unroll
    for (int i = tid; i < (F_IN * HID) / 4; i += 256)
        ((float4*)sW1)[i] = ((const float4*)W1)[i];
    __syncthreads();

    int row0 = gblk * 512 + tid;
    int row1 = row0 + 256;
    if (row0 >= n) return;
    bool has1 = (row1 < n);
    int row1c = has1 ? row1 : row0;

    unsigned long long acc0[8], acc1[8];
    #pragma unroll
    for (int p = 0; p < 8; p++) { acc0[p] = 0ull; acc1[p] = 0ull; }

    const float4* xb0 = (const float4*)(X + (size_t)row0 * F_IN);
    const float4* xb1 = (const float4*)(X + (size_t)row1c * F_IN);

    for (int c = 0; c < F_IN / 4; c++) {
        float4 x0 = __ldcs(xb0 + c);
        float4 x1 = __ldcs(xb1 + c);
        const float xs0[4] = {x0.x, x0.y, x0.z, x0.w};
        const float xs1[4] = {x1.x, x1.y, x1.z, x1.w};
        #pragma unroll
        for (int k = 0; k < 4; k++) {
            unsigned long long xp0 = pack2(xs0[k]);
            unsigned long long xp1 = pack2(xs1[k]);
            const unsigned long long* w =
                (const unsigned long long*)&sW1[(4 * c + k) * HID];
            #pragma unroll
            for (int p = 0; p < 8; p++) {
                unsigned long long wp = w[p];
                fma2(acc0[p], xp0, wp);
                fma2(acc1[p], xp1, wp);
            }
        }
    }

    #pragma unroll
    for (int p = 0; p < 8; p += 2) {
        float2 a = unpack2(acc0[p]);
        float2 b = unpack2(acc0[p + 1]);
        g_hpreh[row0 * 4 + p / 2] = pack_half4(a.x, a.y, b.x, b.y);
    }
    if (has1) {
        #pragma unroll
        for (int p = 0; p < 8; p += 2) {
            float2 a = unpack2(acc1[p]);
            float2 b = unpack2(acc1[p + 1]);
            g_hpreh[row1 * 4 + p / 2] = pack_half4(a.x, a.y, b.x, b.y);
        }
    }
}

__device__ __forceinline__ void conv_one(const void* __restrict__ src,
                                         const void* __restrict__ dst,
                                         int fmt, int e, int n) {
    int s = load_idx(src, fmt, e, n);
    int d = load_idx(dst, fmt, e, n);
    atomicAdd(&g_deg_out[s], 1);
    int slot = atomicAdd(&g_deg_in[d], 1);
    slot = slot > 8191 ? 8191 : slot;
    g_dslot[e] = (d << 13) | slot;
}

__global__ void __launch_bounds__(256)
k_fused1(const float* __restrict__ X, const float* __restrict__ W1,
         const void* __restrict__ src, const void* __restrict__ dst,
         int ecount, int n, int gemm_blocks) {
    __shared__ float sW1[F_IN * HID];   // gemm role (32 KB)
    __shared__ int shflags[4];
    if (blockIdx.x == 0 && threadIdx.x == 0) c_scan = 0;  // reset for k_scancsr
    if ((int)blockIdx.x < gemm_blocks) {
        gemm1_part(X, W1, sW1, blockIdx.x, n);
    } else {
        int fmt = probe_fmt(src, ecount, n, shflags);
        int e = (blockIdx.x - gemm_blocks) * 512 + threadIdx.x;
        if (e < ecount) conv_one(src, dst, fmt, e, n);
        if (e + 256 < ecount) conv_one(src, dst, fmt, e + 256, n);
    }
}

// ---------------- scan role (decoupled lookback) + norms + hpreh scale ----------------
__device__ __forceinline__ void scan_part(int b, int n, int* wsum, int* bexcl_s) {
    int tid = threadIdx.x, lane = tid & 31, wid = tid >> 5;
    int i = b * 256 + tid;
    int v = (i < n) ? g_deg_in[i] : 0;
    int s = v;
    #pragma unroll
    for (int off = 1; off < 32; off <<= 1) {
        int t = __shfl_up_sync(0xffffffff, s, off);
        if (lane >= off) s += t;
    }
    if (lane == 31) wsum[wid] = s;
    __syncthreads();

    if (wid == 0) {
        int w = (lane < 8) ? wsum[lane] : 0;
        #pragma unroll
        for (int off = 1; off < 8; off <<= 1) {
            int t = __shfl_up_sync(0xffffffff, w, off);
            if (lane >= off) w += t;
        }
        if (lane < 8) wsum[lane] = w;
        int T = __shfl_sync(0xffffffff, w, 7);

        if (lane == 0) {
            unsigned long long pk =
                ((unsigned long long)((b == 0) ? 2u : 1u) << 32) | (unsigned)T;
            *((volatile unsigned long long*)&g_lb[b]) = pk;
        }
        int running = 0;
        if (b > 0) {
            int tile = b - 1;
            while (true) {
                int idx = tile - lane;
                int flag, val;
                if (idx >= 0) {
                    unsigned long long x;
                    do {
                        x = *((volatile unsigned long long*)&g_lb[idx]);
                        flag = (int)(x >> 32);
                    } while (flag == 0);
                    val = (int)(unsigned)(x & 0xffffffffull);
                } else { flag = 1; val = 0; }
                unsigned mp = __ballot_sync(0xffffffff, flag == 2);
                if (mp) {
                    int first = __ffs(mp) - 1;
                    int contrib = (lane <= first) ? val : 0;
                    #pragma unroll
                    for (int o = 16; o; o >>= 1)
                        contrib += __shfl_xor_sync(0xffffffff, contrib, o);
                    running += contrib;
                    break;
                } else {
                    int contrib = val;
                    #pragma unroll
                    for (int o = 16; o; o >>= 1)
                        contrib += __shfl_xor_sync(0xffffffff, contrib, o);
                    running += contrib;
                    tile -= 32;
                }
            }
            if (lane == 0) {
                unsigned long long pk = (2ull << 32) | (unsigned)(running + T);
                *((volatile unsigned long long*)&g_lb[b]) = pk;
            }
        }
        if (lane == 0) *bexcl_s = running;
    }
    __syncthreads();

    int base = *bexcl_s + ((wid > 0) ? wsum[wid - 1] : 0);
    if (i < n) {
        g_row_start[i] = base + s - v;
        int dout = g_deg_out[i]; if (dout < 1) dout = 1;
        int din  = v;            if (din  < 1) din  = 1;
        float nsv = rsqrtf((float)dout);
        g_norm_src[i] = nsv;
        g_norm_dst[i] = rsqrtf((float)din);
        g_deg_out[i] = 0;   // self-clean for next replay
        g_deg_in[i]  = 0;
        #pragma unroll
        for (int q = 0; q < 4; q++) {
            uint2 t = g_hpreh[i * 4 + q];
            float2 f0 = __half22float2(u2h(t.x));
            float2 f1 = __half22float2(u2h(t.y));
            g_hpreh[i * 4 + q] =
                pack_half4(f0.x * nsv, f0.y * nsv, f1.x * nsv, f1.y * nsv);
        }
    }
}

// ---------------- merged scan + csr fill ----------------
// First B_scan blocks run scan and signal; ALL blocks then wait (~scan
// duration, all producers co-resident in wave 1) and fill their csr chunk.
__global__ void __launch_bounds__(256)
k_scancsr(const void* __restrict__ src, int ecount, int n, int B_scan) {
    __shared__ int smisc[12];   // wsum[8] + bexcl + flags reuse
    __shared__ int shflags[4];
    int b = blockIdx.x;
    int tid = threadIdx.x;

    if (b < B_scan) {
        scan_part(b, n, smisc, smisc + 8);
        __syncthreads();
        if (tid == 0) { __threadfence(); atomicAdd(&c_scan, 1); }
    }

    int fmt = probe_fmt(src, ecount, n, shflags);

    if (tid == 0) {
        while (atomicAdd(&c_scan, 0) < B_scan) __nanosleep(64);
        __threadfence();
    }
    __syncthreads();

    if (b == 0) {   // scan fully done -> safe to clean lookback for next replay
        g_lb[tid] = 0ull;
        g_lb[tid + 256] = 0ull;
    }
    int e = b * 512 + tid;
    if (e < ecount) {
        int s  = load_idx(src, fmt, e, n);
        int ps = __ldcs(&g_dslot[e]);
        g_csr[g_row_start[ps >> 13] + (ps & 8191)] = s << 5;
    }
    e += 256;
    if (e < ecount) {
        int s  = load_idx(src, fmt, e, n);
        int ps = __ldcs(&g_dslot[e]);
        g_csr[g_row_start[ps >> 13] + (ps & 8191)] = s << 5;
    }
}

// ---------------- gather-sum: 4 nodes/warp, 8 lanes/node ----------------
__device__ __forceinline__ void gather_sum4(const uint2* __restrict__ table,
                                            int start, int end, int lane,
                                            float& ax, float& ay,
                                            float& az, float& aw) {
    int sub = lane & 3;
    int grp = (lane >> 2) & 1;
    int deg = end - start;
    int main_end = start + (deg & ~7);
    const char* tbl = (const char*)table + sub * 8;

    ax = ay = az = aw = 0.f;
    for (int e = start + 4 * grp; e < main_end; e += 8) {
        int o0 = __ldg(&g_csr[e]);
        int o1 = __ldg(&g_csr[e + 1]);
        int o2 = __ldg(&g_csr[e + 2]);
        int o3 = __ldg(&g_csr[e + 3]);
        uint2 q0 = *(const uint2*)(tbl + o0);
        uint2 q1 = *(const uint2*)(tbl + o1);
        uint2 q2 = *(const uint2*)(tbl + o2);
        uint2 q3 = *(const uint2*)(tbl + o3);
        __half2 hx0 = __hadd2(u2h(q0.x), u2h(q1.x));
        __half2 hx1 = __hadd2(u2h(q2.x), u2h(q3.x));
        __half2 hy0 = __hadd2(u2h(q0.y), u2h(q1.y));
        __half2 hy1 = __hadd2(u2h(q2.y), u2h(q3.y));
        float2 f0 = __half22float2(hx0);
        float2 f1 = __half22float2(hx1);
        float2 g0 = __half22float2(hy0);
        float2 g1 = __half22float2(hy1);
        ax += f0.x + f1.x; ay += f0.y + f1.y;
        az += g0.x + g1.x; aw += g0.y + g1.y;
    }
    for (int e = main_end + grp; e < end; e += 2) {
        int o0 = __ldg(&g_csr[e]);
        uint2 q0 = *(const uint2*)(tbl + o0);
        float2 f0 = __half22float2(u2h(q0.x));
        float2 g0 = __half22float2(u2h(q0.y));
        ax += f0.x; ay += f0.y; az += g0.x; aw += g0.y;
    }
    ax += __shfl_xor_sync(0xffffffff, ax, 4);
    ay += __shfl_xor_sync(0xffffffff, ay, 4);
    az += __shfl_xor_sync(0xffffffff, az, 4);
    aw += __shfl_xor_sync(0xffffffff, aw, 4);
}

// ---------------- SpMM stage 1 (4 nodes per warp) ----------------
__global__ void __launch_bounds__(256)
k_spmm1(const float* __restrict__ b1, int n, int ecount) {
    int tid = threadIdx.x;
    int lane = tid & 31;
    int w = (blockIdx.x * 256 + tid) >> 5;
    int v = 4 * w + (lane >> 3);
    bool active = (v < n);

    int start = 0, end = 0;
    if (active) {
        start = g_row_start[v];
        end = (v + 1 < n) ? g_row_start[v + 1] : ecount;
    }
    float ax, ay, az, aw;
    gather_sum4(g_hpreh, start, end, lane, ax, ay, az, aw);

    if ((lane & 4) == 0 && active) {
        int sub = lane & 3;
        float nd = g_norm_dst[v];
        float ns = g_norm_src[v];
        float4 bb = ((const float4*)b1)[sub];
        float rx = fmaxf(ax * nd + bb.x, 0.f) * ns;
        float ry = fmaxf(ay * nd + bb.y, 0.f) * ns;
        float rz = fmaxf(az * nd + bb.z, 0.f) * ns;
        float rw = fmaxf(aw * nd + bb.w, 0.f) * ns;
        g_hmidh[v * 4 + sub] = pack_half4(rx, ry, rz, rw);
    }
}

// ---------------- SpMM stage 2 + GEMM2 (4 nodes/warp, f32x2 epilogue) ----------------
// Lane l8 handles column pairs {2*l8, 2*l8+1} + 16*c2, c2 in 0..3.
__global__ void __launch_bounds__(256)
k_spmm2g2(const float* __restrict__ W2, const float* __restrict__ b2,
          float* __restrict__ out, int n, int ecount) {
    __shared__ float sW2[HID * NLAB];
    __shared__ float sb2[NLAB];
    int tid = threadIdx.x;  // 256
    for (int i = tid; i < HID * NLAB; i += 256) sW2[i] = W2[i];
    if (tid < NLAB) sb2[tid] = b2[tid];
    __syncthreads();

    int lane = tid & 31;
    int w = (blockIdx.x * 256 + tid) >> 5;
    int v = 4 * w + (lane >> 3);
    bool active = (v < n);

    int start = 0, end = 0;
    if (active) {
        start = g_row_start[v];
        end = (v + 1 < n) ? g_row_start[v + 1] : ecount;
    }
    float ax, ay, az, aw;
    gather_sum4(g_hmidh, start, end, lane, ax, ay, az, aw);

    // broadcast this octet's 16 h values, pre-packed as f32x2 duplicates
    float nd = active ? g_norm_dst[v] : 0.f;
    int base = lane & 24;
    unsigned long long hp[HID];
    #pragma unroll
    for (int s = 0; s < 4; s++) {
        hp[4 * s + 0] = pack2(__shfl_sync(0xffffffff, ax, base + s) * nd);
        hp[4 * s + 1] = pack2(__shfl_sync(0xffffffff, ay, base + s) * nd);
        hp[4 * s + 2] = pack2(__shfl_sync(0xffffffff, az, base + s) * nd);
        hp[4 * s + 3] = pack2(__shfl_sync(0xffffffff, aw, base + s) * nd);
    }
    if (!active) return;
    int l8 = lane & 7;
    int c0 = 2 * l8;   // first column of each pair
    unsigned long long acc[4];
    #pragma unroll
    for (int c2 = 0; c2 < 4; c2++)
        acc[c2] = packf2(sb2[c0 + 16 * c2], sb2[c0 + 16 * c2 + 1]);
    #pragma unroll
    for (int k = 0; k < HID; k++) {
        const unsigned long long* wrow =
            (const unsigned long long*)&sW2[k * NLAB + c0];
        unsigned long long hk = hp[k];
        #pragma unroll
        for (int c2 = 0; c2 < 4; c2++) fma2(acc[c2], hk, wrow[8 * c2]);
    }
    float2* o = (float2*)(out + v * NLAB + c0);
    #pragma unroll
    for (int c2 = 0; c2 < 4; c2++) o[8 * c2] = unpack2(acc[c2]);
}

// ---------------- launch ----------------
extern "C" void kernel_launch(void* const* d_in, const int* in_sizes, int n_in,
                              void* d_out, int out_size) {
    int n = out_size / NLAB;
    if (n > NMAX) n = NMAX;

    // Identify inputs by element-count signature.
    int idx_X = -1, idx_W1 = -1, idx_b1 = -1, idx_W2 = -1, idx_b2 = -1;
    int idx_e1 = -1, idx_e2 = -1;
    for (int i = 0; i < n_in; i++) {
        int sz = in_sizes[i];
        if (sz == n * F_IN)            idx_X = i;
        else if (sz == F_IN * HID)     idx_W1 = i;
        else if (sz == HID)            idx_b1 = i;
        else if (sz == HID * NLAB)     idx_W2 = i;
        else if (sz == NLAB)           idx_b2 = i;
        else if (idx_e1 < 0)           idx_e1 = i;
        else                           idx_e2 = i;
    }

    // src/dst by ordering convention (see round-3 notes).
    int idx_src, idx_dst;
    if (idx_e1 > idx_X) { idx_src = idx_e1; idx_dst = idx_e2; }
    else                { idx_dst = idx_e1; idx_src = idx_e2; }

    const float* X   = (const float*)d_in[idx_X];
    const float* W1  = (const float*)d_in[idx_W1];
    const float* b1  = (const float*)d_in[idx_b1];
    const float* W2  = (const float*)d_in[idx_W2];
    const float* b2  = (const float*)d_in[idx_b2];
    const void*  esrc = d_in[idx_src];
    const void*  edst = d_in[idx_dst];

    int ecount = in_sizes[idx_src];
    if (ecount > EMAX) ecount = EMAX;

    int gemm_blocks = (n + 511) / 512;
    int conv_blocks = (ecount + 511) / 512;
    int B_scan = (n + 255) / 256;
    int scancsr_blocks = (ecount + 511) / 512;
    if (scancsr_blocks < B_scan) scancsr_blocks = B_scan;

    k_fused1<<<gemm_blocks + conv_blocks, 256>>>(X, W1, esrc, edst,
                                                 ecount, n, gemm_blocks);
    k_scancsr<<<scancsr_blocks, 256>>>(esrc, ecount, n, B_scan);

    int spmm_blocks = (n + 31) / 32;
    k_spmm1<<<spmm_blocks, 256>>>(b1, n, ecount);
    k_spmm2g2<<<spmm_blocks, 256>>>(W2, b2, (float*)d_out, n, ecount);
}